// round 1
// baseline (speedup 1.0000x reference)
#include <cuda_runtime.h>

#define Bn   16
#define Cn   64
#define Hn   256
#define Wn   256
#define OHW  125
#define TOH  16
#define TOW  64

// Persistent scratch (device globals are allowed; allocation APIs are not)
__device__ float  g_weight[Bn * Cn * 64 * 16];   // [b][c][tap=ki*8+kj][nn]  (4 MB)
__device__ float  g_s[Bn * Hn * Wn];             // channel sum of squares   (4 MB)
__device__ float  g_norm[Bn * OHW * OHW];        // box-summed norm          (1 MB)
__device__ double g_part1[1024];                 // deterministic partials
__device__ double g_part2[1024];
__device__ float  g_stdadd;                      // std/10 + 1e-9

__constant__ float cs8[8] = {1.f,  0.70710678118654752f, 0.f, -0.70710678118654752f,
                             -1.f, -0.70710678118654752f, 0.f,  0.70710678118654752f};
__constant__ float sn8[8] = {0.f,  0.70710678118654752f, 1.f,  0.70710678118654752f,
                             0.f, -0.70710678118654752f, -1.f, -0.70710678118654752f};

// ---------------------------------------------------------------------------
// K1: weight generation.  One CUDA block (64 threads) per (b, nn, c) 8x8 tile.
//   f   = rfft2(w, ortho)                      (forward scale 1/8)
//   f'  = Re(f)*A + i*Im(f)*B
//   out = irfft2(f', s=(8,8), ortho)
// irfft2 = ortho ifft along axis0, then c2r along axis1 (Im of DC/Nyquist bins
// along the last axis is ignored — numpy/pocketfft semantics).
// ---------------------------------------------------------------------------
__global__ void wgen_kernel(const float* __restrict__ z, const float* __restrict__ fc) {
    int bid = blockIdx.x;            // 16384 = 16 * 16 * 64
    int b   = bid >> 10;
    int rest = bid & 1023;
    int nn  = rest >> 6;             // ni*4 + nj
    int c   = rest & 63;
    int ni  = nn >> 2, nj = nn & 3;

    __shared__ float w[64];
    __shared__ float Fr[8][5], Fi[8][5];

    int t = threadIdx.x;
    int i = t >> 3, j = t & 7;
    w[t] = z[((b * Cn + c) * 32 + ni * 8 + i) * 32 + (nj * 8 + j)];
    __syncthreads();

    if (t < 40) {
        int u = t / 5, v = t % 5;
        float sr = 0.f, si = 0.f;
        for (int ii = 0; ii < 8; ii++)
            for (int jj = 0; jj < 8; jj++) {
                int m = (u * ii + v * jj) & 7;
                float wv = w[ii * 8 + jj];
                sr += wv * cs8[m];      // e^{-i th} = cos - i sin
                si -= wv * sn8[m];
            }
        sr *= 0.125f; si *= 0.125f;     // ortho forward: 1/sqrt(64)
        Fr[u][v] = sr * fc[(u * 5 + v) * 2 + 0];
        Fi[u][v] = si * fc[(u * 5 + v) * 2 + 1];
    }
    __syncthreads();

    // out[i][j]; combined inverse scale (1/sqrt8)*(1/sqrt8) = 1/8 applied once
    float acc = 0.f;
    #pragma unroll
    for (int v = 0; v <= 4; v++) {
        float gr = 0.f, gi = 0.f;
        #pragma unroll
        for (int u = 0; u < 8; u++) {
            int m = (u * i) & 7;        // e^{+i th}
            gr += Fr[u][v] * cs8[m] - Fi[u][v] * sn8[m];
            gi += Fr[u][v] * sn8[m] + Fi[u][v] * cs8[m];
        }
        if (v == 0)       acc += gr;
        else if (v == 4)  acc += (j & 1) ? -gr : gr;
        else {
            int m = (v * j) & 7;
            acc += 2.f * (gr * cs8[m] - gi * sn8[m]);
        }
    }
    acc *= 0.125f;
    g_weight[((b * Cn + c) * 64 + i * 8 + j) * 16 + nn] = acc;
}

// ---------------------------------------------------------------------------
// K2: s[b,h,w] = sum_c x[b,c,h,w]^2   (single streaming pass over x)
// ---------------------------------------------------------------------------
__global__ void sumsq_kernel(const float* __restrict__ x) {
    int idx = blockIdx.x * 256 + threadIdx.x;      // 1,048,576 threads
    int b  = idx >> 16;
    int hw = idx & 65535;
    const float* xp = x + (size_t)b * Cn * Hn * Wn + hw;
    float s = 0.f;
    #pragma unroll
    for (int c = 0; c < Cn; c++) {
        float v = xp[c * Hn * Wn];
        s += v * v;
    }
    g_s[idx] = s;
}

// ---------------------------------------------------------------------------
// K3: norm[b,oh,ow] = 8x8 stride-2 box sum of s; deterministic double partials
// ---------------------------------------------------------------------------
__global__ void boxnorm_kernel() {
    int idx = blockIdx.x * 256 + threadIdx.x;
    bool valid = idx < Bn * OHW * OHW;
    float acc = 0.f;
    if (valid) {
        int b  = idx / (OHW * OHW);
        int r  = idx % (OHW * OHW);
        int oh = r / OHW, ow = r % OHW;
        const float* sp = g_s + b * Hn * Wn + (2 * oh) * Wn + 2 * ow;
        #pragma unroll
        for (int ki = 0; ki < 8; ki++)
            #pragma unroll
            for (int kj = 0; kj < 8; kj++)
                acc += sp[ki * Wn + kj];
        g_norm[idx] = acc;
    }
    __shared__ double s1[256], s2[256];
    s1[threadIdx.x] = valid ? (double)acc : 0.0;
    s2[threadIdx.x] = valid ? (double)acc * (double)acc : 0.0;
    __syncthreads();
    for (int st = 128; st > 0; st >>= 1) {
        if (threadIdx.x < st) {
            s1[threadIdx.x] += s1[threadIdx.x + st];
            s2[threadIdx.x] += s2[threadIdx.x + st];
        }
        __syncthreads();
    }
    if (threadIdx.x == 0) {
        g_part1[blockIdx.x] = s1[0];
        g_part2[blockIdx.x] = s2[0];
    }
}

// ---------------------------------------------------------------------------
// K4: finalize ddof=1 std over the (16x-replicated) norm tensor
// ---------------------------------------------------------------------------
__global__ void stats_kernel() {
    __shared__ double s1[256], s2[256];
    double a = 0.0, b2 = 0.0;
    for (int i = threadIdx.x; i < 1024; i += 256) { a += g_part1[i]; b2 += g_part2[i]; }
    s1[threadIdx.x] = a; s2[threadIdx.x] = b2;
    __syncthreads();
    for (int st = 128; st > 0; st >>= 1) {
        if (threadIdx.x < st) {
            s1[threadIdx.x] += s1[threadIdx.x + st];
            s2[threadIdx.x] += s2[threadIdx.x + st];
        }
        __syncthreads();
    }
    if (threadIdx.x == 0) {
        double S1 = s1[0] * 16.0;           // each unique value appears 16x
        double S2 = s2[0] * 16.0;
        double Nt = 4000000.0;              // 256 * 125 * 125
        double var = (S2 - S1 * S1 / Nt) / (Nt - 1.0);
        g_stdadd = (float)(sqrt(var) * 0.1 + 1e-9);
    }
}

// ---------------------------------------------------------------------------
// K5: main grouped conv, fp32 direct.
// Block = (group b, 16 oh x 64 ow tile). 256 threads.
// Per-c: x tile (parity-split columns, conflict-free stride-2 taps) + 16x64
// weight slab in smem. Thread owns acc[16 nn][2 oh][2 ow].
// ---------------------------------------------------------------------------
__global__ void __launch_bounds__(256, 2) conv_kernel(const float* __restrict__ x,
                                                      float* __restrict__ out) {
    int b   = blockIdx.z;
    int oh0 = blockIdx.y * TOH;
    int ow0 = blockIdx.x * TOW;

    __shared__ float xs[2][38][68];     // [col parity][row][col/2]
    __shared__ float ws[64][16];        // [tap][nn]

    int tid  = threadIdx.x;
    int warp = tid >> 5, lane = tid & 31;

    float acc[16][2][2];
    #pragma unroll
    for (int n = 0; n < 16; n++)
        #pragma unroll
        for (int p = 0; p < 2; p++)
            #pragma unroll
            for (int q = 0; q < 2; q++) acc[n][p][q] = 0.f;

    int ih0 = 2 * oh0, iw0 = 2 * ow0;
    const float* xb = x + (size_t)b * Cn * Hn * Wn;

    for (int c = 0; c < Cn; c++) {
        __syncthreads();
        const float* xc = xb + (size_t)c * Hn * Wn;
        for (int li = tid; li < 38 * 134; li += 256) {
            int r  = li / 134, cc = li % 134;
            int ih = ih0 + r,  iw = iw0 + cc;
            float v = (ih < Hn && iw < Wn) ? xc[ih * Wn + iw] : 0.f;
            xs[cc & 1][r][cc >> 1] = v;
        }
        const float* wp = g_weight + ((size_t)b * Cn + c) * 64 * 16;
        for (int li = tid; li < 1024; li += 256) ws[li >> 4][li & 15] = wp[li];
        __syncthreads();

        #pragma unroll 1
        for (int ki = 0; ki < 8; ki++) {
            int r0 = 2 * warp + ki;
            int r1 = 2 * (warp + 8) + ki;
            #pragma unroll
            for (int kj = 0; kj < 8; kj++) {
                int par = kj & 1, off = kj >> 1;
                float xv00 = xs[par][r0][lane + off];
                float xv01 = xs[par][r0][lane + 32 + off];
                float xv10 = xs[par][r1][lane + off];
                float xv11 = xs[par][r1][lane + 32 + off];
                #pragma unroll
                for (int n = 0; n < 16; n++) {
                    float wv = ws[ki * 8 + kj][n];
                    acc[n][0][0] += wv * xv00;
                    acc[n][0][1] += wv * xv01;
                    acc[n][1][0] += wv * xv10;
                    acc[n][1][1] += wv * xv11;
                }
            }
        }
    }

    float stdadd = g_stdadd;
    #pragma unroll
    for (int op = 0; op < 2; op++) {
        int oh = oh0 + warp + 8 * op;
        if (oh >= OHW) continue;
        #pragma unroll
        for (int oq = 0; oq < 2; oq++) {
            int ow = ow0 + lane + 32 * oq;
            if (ow >= OHW) continue;
            float nrm = g_norm[b * OHW * OHW + oh * OHW + ow];
            float fac = 0.01f / sqrtf(nrm + stdadd);
            #pragma unroll
            for (int n = 0; n < 16; n++)
                out[(((size_t)b * 16 + n) * OHW + oh) * OHW + ow] = acc[n][op][oq] * fac;
        }
    }
}

extern "C" void kernel_launch(void* const* d_in, const int* in_sizes, int n_in,
                              void* d_out, int out_size) {
    const float* x  = (const float*)d_in[0];   // [16,64,256,256]
    const float* z  = (const float*)d_in[1];   // [16,64,32,32]
    const float* fc = (const float*)d_in[2];   // [8,5,2]
    float* out = (float*)d_out;                // [16,16,125,125]

    wgen_kernel<<<16384, 64>>>(z, fc);
    sumsq_kernel<<<4096, 256>>>(x);
    boxnorm_kernel<<<(Bn * OHW * OHW + 255) / 256, 256>>>();
    stats_kernel<<<1, 256>>>();
    conv_kernel<<<dim3(2, 8, Bn), 256>>>(x, out);
}